// round 1
// baseline (speedup 1.0000x reference)
#include <cuda_runtime.h>

#define BB 64
#define TT 512
#define DD 1024
#define NBLK 128
#define EPSV 1e-6f

// ---------------- device scratch (no allocations allowed) ----------------
__device__ float g_xtau[(size_t)BB * TT * DD];     // 134 MB
__device__ float g_mem [(size_t)BB * TT * DD];     // 134 MB
__device__ float g_tauT[DD * BB];                  // tau transposed: tauT[e*64+b] = tau[b][e]
__device__ float g_partial[8 * BB * DD];           // split-K partials [kc][b][e]
__device__ unsigned int g_bar;
__device__ unsigned int g_gen;

// ---------------- big GEMM: out[m][e] = sum_k x[m][k]*W[k][e] + bias[e] ----------------
// M=32768, N=1024, K=1024. blockIdx.z: 0 -> (W_tau[:D], b_tau, g_xtau), 1 -> (W_mem, b_mem, g_mem)
__global__ void __launch_bounds__(256) gemm_kernel(
    const float* __restrict__ x,
    const float* __restrict__ Wt, const float* __restrict__ bt,
    const float* __restrict__ Wm, const float* __restrict__ bm)
{
    const float* W;
    const float* bias;
    float* out;
    if (blockIdx.z == 0) { W = Wt; bias = bt; out = g_xtau; }
    else                 { W = Wm; bias = bm; out = g_mem;  }

    __shared__ __align__(16) float As[16][68];   // [k][m], padded: 68*4=272 bytes, 16B-aligned rows
    __shared__ __align__(16) float Bs[16][64];   // [k][n]

    const int tid = threadIdx.x;
    const int tx = tid & 15;        // n direction
    const int ty = tid >> 4;        // m direction
    const int m0 = blockIdx.y * 64;
    const int n0 = blockIdx.x * 64;

    float acc[4][4] = {};

    for (int k0 = 0; k0 < 1024; k0 += 16) {
        // A tile 64x16 -> transposed into As[k][m]
        {
            int r  = tid >> 2;   // 0..63 row
            int c4 = tid & 3;    // 0..3 float4 within 16 k
            float4 a = *(const float4*)&x[(size_t)(m0 + r) * 1024 + k0 + c4 * 4];
            As[c4 * 4 + 0][r] = a.x;
            As[c4 * 4 + 1][r] = a.y;
            As[c4 * 4 + 2][r] = a.z;
            As[c4 * 4 + 3][r] = a.w;
        }
        // B tile 16x64
        {
            int r  = tid >> 4;   // 0..15 k
            int c4 = tid & 15;   // 0..15 float4
            *(float4*)&Bs[r][c4 * 4] =
                *(const float4*)&W[(size_t)(k0 + r) * 1024 + n0 + c4 * 4];
        }
        __syncthreads();

#pragma unroll
        for (int kk = 0; kk < 16; kk++) {
            float4 a = *(const float4*)&As[kk][ty * 4];
            float4 b = *(const float4*)&Bs[kk][tx * 4];
            float av[4] = {a.x, a.y, a.z, a.w};
            float bv[4] = {b.x, b.y, b.z, b.w};
#pragma unroll
            for (int i = 0; i < 4; i++)
#pragma unroll
                for (int j = 0; j < 4; j++)
                    acc[i][j] = fmaf(av[i], bv[j], acc[i][j]);
        }
        __syncthreads();
    }

    float4 bb = *(const float4*)&bias[n0 + tx * 4];
    float bv[4] = {bb.x, bb.y, bb.z, bb.w};
#pragma unroll
    for (int i = 0; i < 4; i++) {
        float4 o;
        o.x = acc[i][0] + bv[0];
        o.y = acc[i][1] + bv[1];
        o.z = acc[i][2] + bv[2];
        o.w = acc[i][3] + bv[3];
        *(float4*)&out[(size_t)(m0 + ty * 4 + i) * 1024 + n0 + tx * 4] = o;
    }
}

// ---------------- software grid barrier (all NBLK blocks co-resident) ----------------
__device__ __forceinline__ void gridbar()
{
    __threadfence();                 // make this thread's global writes visible
    __syncthreads();
    if (threadIdx.x == 0) {
        unsigned int g = *(volatile unsigned int*)&g_gen;
        if (atomicAdd(&g_bar, 1) == NBLK - 1) {
            atomicExch(&g_bar, 0);
            __threadfence();
            atomicAdd(&g_gen, 1);
        } else {
            while (*(volatile unsigned int*)&g_gen == g) { }
        }
    }
    __syncthreads();
}

// ---------------- persistent recurrence kernel ----------------
// 128 blocks: bid -> (kc = bid>>4 in [0,8): K-chunk of 128, nc = bid&15 in [0,16): 64-col chunk)
// Phase 1: partial[kc][b][e] = sum_{k in chunk} tau[b][k] * W_tt[k][e]   (W chunk resident in smem)
// Phase 2: block (kc,nc) finalizes b in [kc*8, kc*8+8), e in [nc*64, nc*64+64):
//          tau=sigmoid(xtau + sum partials); alpha=exp(-1/(tau+eps)); v,spike update.
//          v, thresh live in registers across all 512 steps.
__global__ void __launch_bounds__(256) recur_kernel(
    const float* __restrict__ Wtau,
    const float* __restrict__ log_thresh,
    float* __restrict__ out)
{
    extern __shared__ float sm[];
    float (*Ws)[64] = (float(*)[64])sm;              // [128][64] persistent W_tt chunk (32KB)
    float (*ts)[64] = (float(*)[64])(sm + 128 * 64); // [128][64] tau chunk, tauT layout (32KB)

    const int tid = threadIdx.x;
    const int bid = blockIdx.x;
    const int nc = bid & 15;
    const int kc = bid >> 4;
    const int tx = tid & 15;   // e direction (4 cols each)
    const int ty = tid >> 4;   // b direction (4 rows each)

    const float* Wtt = Wtau + (size_t)DD * DD;   // rows D..2D-1 of W_tau

    // Load persistent W_tt chunk: k in [kc*128, +128), e in [nc*64, +64)
#pragma unroll
    for (int i = 0; i < 8; i++) {
        int idx4 = tid + i * 256;     // 0..2047 float4s
        int k = idx4 >> 4;
        int c = idx4 & 15;
        *(float4*)&Ws[k][c * 4] =
            *(const float4*)&Wtt[(size_t)(kc * 128 + k) * 1024 + nc * 64 + c * 4];
    }

    // Init tau0 = 1.0 (this block's 512-element slice of g_tauT)
    {
        int base = bid * 512;
        g_tauT[base + tid] = 1.0f;
        g_tauT[base + 256 + tid] = 1.0f;
    }

    // Static per-thread phase-2 ownership (2 outputs): b in [kc*8,+8), e in [nc*64,+64)
    const int oi0 = tid, oi1 = tid + 256;
    const int b0 = kc * 8 + (oi0 >> 6), e0 = nc * 64 + (oi0 & 63);
    const int b1 = kc * 8 + (oi1 >> 6), e1 = nc * 64 + (oi1 & 63);
    float v0 = 0.f, v1 = 0.f;
    const float th0 = 1.f / (1.f + expf(-log_thresh[e0]));
    const float th1 = 1.f / (1.f + expf(-log_thresh[e1]));

    float* out_tau = out + (size_t)BB * TT * DD;
    float* out_v   = out_tau + BB * DD;
    float* out_th  = out_v + BB * DD;

    gridbar();   // tau0 init visible everywhere

#pragma unroll 1
    for (int t = 0; t < TT; t++) {
        // ---- phase 1: load tau chunk (tauT[k][b], contiguous slab), then partial GEMM
#pragma unroll
        for (int i = 0; i < 8; i++) {
            int idx4 = tid + i * 256;
            float4 v4 = __ldcg((const float4*)&g_tauT[kc * 128 * 64 + idx4 * 4]);
            *(float4*)&((float*)ts)[idx4 * 4] = v4;
        }
        __syncthreads();

        float acc[4][4] = {};
#pragma unroll 4
        for (int kk = 0; kk < 128; kk++) {
            float4 a = *(const float4*)&ts[kk][ty * 4];
            float4 w = *(const float4*)&Ws[kk][tx * 4];
            float av[4] = {a.x, a.y, a.z, a.w};
            float wv[4] = {w.x, w.y, w.z, w.w};
#pragma unroll
            for (int i = 0; i < 4; i++)
#pragma unroll
                for (int j = 0; j < 4; j++)
                    acc[i][j] = fmaf(av[i], wv[j], acc[i][j]);
        }
#pragma unroll
        for (int i = 0; i < 4; i++) {
            int b = ty * 4 + i;
            float4 o = make_float4(acc[i][0], acc[i][1], acc[i][2], acc[i][3]);
            *(float4*)&g_partial[(size_t)(kc * 64 + b) * 1024 + nc * 64 + tx * 4] = o;
        }

        gridbar();   // all partials visible

        // ---- phase 2: finalize 2 owned (b,e) outputs
        {
            // output 0
            float sum = g_xtau[(size_t)(b0 * TT + t) * DD + e0];
#pragma unroll
            for (int p = 0; p < 8; p++)
                sum += __ldcg(&g_partial[(size_t)(p * 64 + b0) * 1024 + e0]);
            float tau = 1.f / (1.f + expf(-sum));
            float alpha = expf(-1.f / (tau + EPSV));
            float memv = g_mem[(size_t)(b0 * TT + t) * DD + e0];
            v0 = alpha * v0 + (1.f - alpha) * memv;
            float s = (v0 >= th0) ? 1.f : 0.f;
            v0 = v0 * (1.f - s);
            out[(size_t)(b0 * TT + t) * DD + e0] = s;
            g_tauT[e0 * 64 + b0] = tau;
            if (t == TT - 1) {
                out_tau[b0 * DD + e0] = tau;
                out_v[b0 * DD + e0] = v0;
                if (b0 == 0) out_th[e0] = th0;
            }
        }
        {
            // output 1
            float sum = g_xtau[(size_t)(b1 * TT + t) * DD + e1];
#pragma unroll
            for (int p = 0; p < 8; p++)
                sum += __ldcg(&g_partial[(size_t)(p * 64 + b1) * 1024 + e1]);
            float tau = 1.f / (1.f + expf(-sum));
            float alpha = expf(-1.f / (tau + EPSV));
            float memv = g_mem[(size_t)(b1 * TT + t) * DD + e1];
            v1 = alpha * v1 + (1.f - alpha) * memv;
            float s = (v1 >= th1) ? 1.f : 0.f;
            v1 = v1 * (1.f - s);
            out[(size_t)(b1 * TT + t) * DD + e1] = s;
            g_tauT[e1 * 64 + b1] = tau;
            if (t == TT - 1) {
                out_tau[b1 * DD + e1] = tau;
                out_v[b1 * DD + e1] = v1;
                if (b1 == 0) out_th[e1] = th1;
            }
        }

        gridbar();   // new tauT visible before next step's phase 1
    }
}

// ---------------- launcher ----------------
extern "C" void kernel_launch(void* const* d_in, const int* in_sizes, int n_in,
                              void* d_out, int out_size)
{
    const float* x    = (const float*)d_in[0];   // (64,512,1024)
    const float* Wtau = (const float*)d_in[1];   // (2048,1024)
    const float* btau = (const float*)d_in[2];   // (1024,)
    const float* Wmem = (const float*)d_in[3];   // (1024,1024)
    const float* bmem = (const float*)d_in[4];   // (1024,)
    const float* lth  = (const float*)d_in[5];   // (1024,)
    float* out = (float*)d_out;

    (void)in_sizes; (void)n_in; (void)out_size;

    cudaFuncSetAttribute(recur_kernel,
                         cudaFuncAttributeMaxDynamicSharedMemorySize, 65536);

    dim3 g1(16, 512, 2);     // N/64, M/64, {x_tau, mem}
    gemm_kernel<<<g1, 256>>>(x, Wtau, btau, Wmem, bmem);

    recur_kernel<<<NBLK, 256, 65536>>>(Wtau, lth, out);
}

// round 7
// speedup vs baseline: 1.0712x; 1.0712x over previous
#include <cuda_runtime.h>

#define BB 64
#define TT 512
#define DD 1024
#define NBLK 128
#define EPSV 1e-6f

typedef unsigned long long u64;

// packed fp32x2 FMA: c = a*b + c (elementwise, exact IEEE fp32 per lane)
#define FMA2(c, a, b) \
    asm("fma.rn.f32x2 %0, %1, %2, %3;" : "=l"(c) : "l"(a), "l"(b), "l"(c))

__device__ __forceinline__ u64 pack2(float x) {
    u64 r;
    asm("mov.b64 %0, {%1, %1};" : "=l"(r) : "r"(__float_as_uint(x)));
    return r;
}
__device__ __forceinline__ float2 unpack2(u64 v) {
    float2 f;
    asm("mov.b64 {%0, %1}, %2;" : "=f"(f.x), "=f"(f.y) : "l"(v));
    return f;
}

// ---------------- device scratch (no allocations allowed) ----------------
__device__ float g_xtau[(size_t)BB * TT * DD];     // 134 MB
__device__ float g_mem [(size_t)BB * TT * DD];     // 134 MB
__device__ float g_tauT[DD * BB];                  // tau transposed: tauT[e*64+b]
__device__ float g_partial[8 * BB * DD];           // split-K partials [kc][b][e]
__device__ unsigned int g_bar;
__device__ unsigned int g_gen;

// ---------------- big GEMM: out[m][e] = sum_k x[m][k]*W[k][e] + bias[e] ----------------
// M=32768, N=1024, K=1024. z=0 -> (W_tau[:D], b_tau, g_xtau), z=1 -> (W_mem, b_mem, g_mem)
// Double-buffered smem pipeline: 1 __syncthreads per k-tile, LDG overlapped with FMA.
__global__ void __launch_bounds__(256) gemm_kernel(
    const float* __restrict__ x,
    const float* __restrict__ Wt, const float* __restrict__ bt,
    const float* __restrict__ Wm, const float* __restrict__ bm)
{
    const float* W;
    const float* bias;
    float* out;
    if (blockIdx.z == 0) { W = Wt; bias = bt; out = g_xtau; }
    else                 { W = Wm; bias = bm; out = g_mem;  }

    __shared__ __align__(16) float As[2][16][68];   // [buf][k][m] padded
    __shared__ __align__(16) float Bs[2][16][64];   // [buf][k][n]

    const int tid = threadIdx.x;
    const int tx = tid & 15;        // n direction
    const int ty = tid >> 4;        // m direction
    const int m0 = blockIdx.y * 64;
    const int n0 = blockIdx.x * 64;

    // per-thread load coordinates
    const int ar  = tid >> 2;        // A row 0..63
    const int ac4 = tid & 3;         // A float4 index within 16 k
    const int br  = tid >> 4;        // B k-row 0..15
    const int bc4 = tid & 15;        // B float4 index 0..15

    const float* a_src = &x[(size_t)(m0 + ar) * 1024 + ac4 * 4];
    const float* b_src = &W[(size_t)br * 1024 + n0 + bc4 * 4];

    // prologue: load tile 0 into buffer 0
    {
        float4 a = *(const float4*)a_src;
        As[0][ac4 * 4 + 0][ar] = a.x;
        As[0][ac4 * 4 + 1][ar] = a.y;
        As[0][ac4 * 4 + 2][ar] = a.z;
        As[0][ac4 * 4 + 3][ar] = a.w;
        *(float4*)&Bs[0][br][bc4 * 4] = *(const float4*)b_src;
    }
    __syncthreads();

    // acc[p][j]: f32x2 pair over m rows (ty*4+2p, ty*4+2p+1), col n0+tx*4+j
    u64 acc[2][4] = {};

    for (int k0 = 0; k0 < 1024; k0 += 16) {
        const int cur = (k0 >> 4) & 1;
        const bool has_next = (k0 + 16) < 1024;

        // issue next-tile global loads early (latency hidden under compute)
        float4 a_n, b_n;
        if (has_next) {
            a_n = *(const float4*)(a_src + k0 + 16);
            b_n = *(const float4*)(b_src + (size_t)(k0 + 16) * 1024);
        }

#pragma unroll
        for (int kk = 0; kk < 16; kk++) {
            ulonglong2 a = *(const ulonglong2*)&As[cur][kk][ty * 4];   // 2 m-pairs
            float4 b = *(const float4*)&Bs[cur][kk][tx * 4];
            u64 b0 = pack2(b.x), b1 = pack2(b.y), b2 = pack2(b.z), b3 = pack2(b.w);
            FMA2(acc[0][0], a.x, b0); FMA2(acc[0][1], a.x, b1);
            FMA2(acc[0][2], a.x, b2); FMA2(acc[0][3], a.x, b3);
            FMA2(acc[1][0], a.y, b0); FMA2(acc[1][1], a.y, b1);
            FMA2(acc[1][2], a.y, b2); FMA2(acc[1][3], a.y, b3);
        }

        if (has_next) {
            const int nxt = cur ^ 1;
            As[nxt][ac4 * 4 + 0][ar] = a_n.x;
            As[nxt][ac4 * 4 + 1][ar] = a_n.y;
            As[nxt][ac4 * 4 + 2][ar] = a_n.z;
            As[nxt][ac4 * 4 + 3][ar] = a_n.w;
            *(float4*)&Bs[nxt][br][bc4 * 4] = b_n;
            __syncthreads();
        }
    }

    float4 bb = *(const float4*)&bias[n0 + tx * 4];
#pragma unroll
    for (int p = 0; p < 2; p++) {
        float2 c0 = unpack2(acc[p][0]);
        float2 c1 = unpack2(acc[p][1]);
        float2 c2 = unpack2(acc[p][2]);
        float2 c3 = unpack2(acc[p][3]);
        int r = m0 + ty * 4 + 2 * p;
        float4 o0 = make_float4(c0.x + bb.x, c1.x + bb.y, c2.x + bb.z, c3.x + bb.w);
        float4 o1 = make_float4(c0.y + bb.x, c1.y + bb.y, c2.y + bb.z, c3.y + bb.w);
        *(float4*)&out[(size_t)r * 1024 + n0 + tx * 4] = o0;
        *(float4*)&out[(size_t)(r + 1) * 1024 + n0 + tx * 4] = o1;
    }
}

// ---------------- software grid barrier (all NBLK blocks co-resident) ----------------
__device__ __forceinline__ void gridbar()
{
    __threadfence();
    __syncthreads();
    if (threadIdx.x == 0) {
        unsigned int g = *(volatile unsigned int*)&g_gen;
        if (atomicAdd(&g_bar, 1) == NBLK - 1) {
            atomicExch(&g_bar, 0);
            __threadfence();
            atomicAdd(&g_gen, 1);
        } else {
            while (*(volatile unsigned int*)&g_gen == g) { }
        }
    }
    __syncthreads();
}

// ---------------- persistent recurrence kernel ----------------
__global__ void __launch_bounds__(256) recur_kernel(
    const float* __restrict__ Wtau,
    const float* __restrict__ log_thresh,
    float* __restrict__ out)
{
    extern __shared__ float sm[];
    float (*Ws)[64] = (float(*)[64])sm;              // [128][64] persistent W_tt chunk
    float (*ts)[64] = (float(*)[64])(sm + 128 * 64); // [128][64] tau chunk (tauT layout)

    const int tid = threadIdx.x;
    const int bid = blockIdx.x;
    const int nc = bid & 15;
    const int kc = bid >> 4;
    const int tx = tid & 15;   // e direction
    const int ty = tid >> 4;   // b direction

    const float* Wtt = Wtau + (size_t)DD * DD;

    // Load persistent W_tt chunk: k in [kc*128,+128), e in [nc*64,+64)
#pragma unroll
    for (int i = 0; i < 8; i++) {
        int idx4 = tid + i * 256;
        int k = idx4 >> 4;
        int c = idx4 & 15;
        *(float4*)&Ws[k][c * 4] =
            *(const float4*)&Wtt[(size_t)(kc * 128 + k) * 1024 + nc * 64 + c * 4];
    }

    // tau0 = 1.0
    {
        int base = bid * 512;
        g_tauT[base + tid] = 1.0f;
        g_tauT[base + 256 + tid] = 1.0f;
    }

    // Static per-thread phase-2 ownership (2 outputs)
    const int oi0 = tid, oi1 = tid + 256;
    const int b0 = kc * 8 + (oi0 >> 6), e0 = nc * 64 + (oi0 & 63);
    const int b1 = kc * 8 + (oi1 >> 6), e1 = nc * 64 + (oi1 & 63);
    float v0 = 0.f, v1 = 0.f;
    const float th0 = 1.f / (1.f + expf(-log_thresh[e0]));
    const float th1 = 1.f / (1.f + expf(-log_thresh[e1]));

    float* out_tau = out + (size_t)BB * TT * DD;
    float* out_v   = out_tau + BB * DD;
    float* out_th  = out_v + BB * DD;

    gridbar();

#pragma unroll 1
    for (int t = 0; t < TT; t++) {
        // Prefetch phase-2 operands (constant data; latency hides under phase 1)
        const size_t i0 = (size_t)(b0 * TT + t) * DD + e0;
        const size_t i1 = (size_t)(b1 * TT + t) * DD + e1;
        float pf_xt0 = __ldg((const float*)&g_xtau[i0]);
        float pf_mm0 = __ldg((const float*)&g_mem[i0]);
        float pf_xt1 = __ldg((const float*)&g_xtau[i1]);
        float pf_mm1 = __ldg((const float*)&g_mem[i1]);

        // ---- phase 1: load tau chunk, partial GEMM with f32x2
#pragma unroll
        for (int i = 0; i < 8; i++) {
            int idx4 = tid + i * 256;
            float4 v4 = __ldcg((const float4*)&g_tauT[kc * 128 * 64 + idx4 * 4]);
            *(float4*)&((float*)ts)[idx4 * 4] = v4;
        }
        __syncthreads();

        u64 acc[2][4] = {};
#pragma unroll 4
        for (int kk = 0; kk < 128; kk++) {
            ulonglong2 a = *(const ulonglong2*)&ts[kk][ty * 4];   // 2 b-pairs
            float4 w = *(const float4*)&Ws[kk][tx * 4];
            u64 w0 = pack2(w.x), w1 = pack2(w.y), w2 = pack2(w.z), w3 = pack2(w.w);
            FMA2(acc[0][0], a.x, w0); FMA2(acc[0][1], a.x, w1);
            FMA2(acc[0][2], a.x, w2); FMA2(acc[0][3], a.x, w3);
            FMA2(acc[1][0], a.y, w0); FMA2(acc[1][1], a.y, w1);
            FMA2(acc[1][2], a.y, w2); FMA2(acc[1][3], a.y, w3);
        }
#pragma unroll
        for (int p = 0; p < 2; p++) {
            float2 c0 = unpack2(acc[p][0]);
            float2 c1 = unpack2(acc[p][1]);
            float2 c2 = unpack2(acc[p][2]);
            float2 c3 = unpack2(acc[p][3]);
            int b = ty * 4 + 2 * p;
            *(float4*)&g_partial[(size_t)(kc * 64 + b) * 1024 + nc * 64 + tx * 4] =
                make_float4(c0.x, c1.x, c2.x, c3.x);
            *(float4*)&g_partial[(size_t)(kc * 64 + b + 1) * 1024 + nc * 64 + tx * 4] =
                make_float4(c0.y, c1.y, c2.y, c3.y);
        }

        gridbar();   // all partials visible

        // ---- phase 2: finalize 2 owned (b,e) outputs
        {
            float sum = pf_xt0;
#pragma unroll
            for (int p = 0; p < 8; p++)
                sum += __ldcg(&g_partial[(size_t)(p * 64 + b0) * 1024 + e0]);
            float tau = 1.f / (1.f + expf(-sum));
            float alpha = expf(-1.f / (tau + EPSV));
            v0 = alpha * v0 + (1.f - alpha) * pf_mm0;
            float s = (v0 >= th0) ? 1.f : 0.f;
            v0 = v0 * (1.f - s);
            out[i0] = s;
            g_tauT[e0 * 64 + b0] = tau;
            if (t == TT - 1) {
                out_tau[b0 * DD + e0] = tau;
                out_v[b0 * DD + e0] = v0;
                if (b0 == 0) out_th[e0] = th0;
            }
        }
        {
            float sum = pf_xt1;
#pragma unroll
            for (int p = 0; p < 8; p++)
                sum += __ldcg(&g_partial[(size_t)(p * 64 + b1) * 1024 + e1]);
            float tau = 1.f / (1.f + expf(-sum));
            float alpha = expf(-1.f / (tau + EPSV));
            v1 = alpha * v1 + (1.f - alpha) * pf_mm1;
            float s = (v1 >= th1) ? 1.f : 0.f;
            v1 = v1 * (1.f - s);
            out[i1] = s;
            g_tauT[e1 * 64 + b1] = tau;
            if (t == TT - 1) {
                out_tau[b1 * DD + e1] = tau;
                out_v[b1 * DD + e1] = v1;
                if (b1 == 0) out_th[e1] = th1;
            }
        }

        gridbar();   // new tauT visible before next step's phase 1
    }
}

// ---------------- launcher ----------------
extern "C" void kernel_launch(void* const* d_in, const int* in_sizes, int n_in,
                              void* d_out, int out_size)
{
    const float* x    = (const float*)d_in[0];
    const float* Wtau = (const float*)d_in[1];
    const float* btau = (const float*)d_in[2];
    const float* Wmem = (const float*)d_in[3];
    const float* bmem = (const float*)d_in[4];
    const float* lth  = (const float*)d_in[5];
    float* out = (float*)d_out;

    (void)in_sizes; (void)n_in; (void)out_size;

    cudaFuncSetAttribute(recur_kernel,
                         cudaFuncAttributeMaxDynamicSharedMemorySize, 65536);

    dim3 g1(16, 512, 2);
    gemm_kernel<<<g1, 256>>>(x, Wtau, btau, Wmem, bmem);

    recur_kernel<<<NBLK, 256, 65536>>>(Wtau, lth, out);
}